// round 10
// baseline (speedup 1.0000x reference)
#include <cuda_runtime.h>
#include <cuda_fp16.h>
#include <cstdint>
#include <math.h>

#define T_STEPS 64
#define B_DIM 2048
#define U_DIM 1024
#define NTILE_U 8             // 1024/128 u-tiles
#define NTILE_B 16            // 2048/128 b-tiles
#define KB 32                 // k elements per chunk
#define NCHUNK (U_DIM / KB)   // 32

// ---------------- persistent state (no allocs allowed) ----------------
__device__ __align__(128) __half g_h_hi[2][B_DIM * U_DIM];
__device__ __align__(128) __half g_h_lo[2][B_DIM * U_DIM];
__device__ __align__(128) __half g_Rt_hi[2 * U_DIM * U_DIM]; // Rt[n][k] = R[k][n]
__device__ __align__(128) __half g_Rt_lo[2 * U_DIM * U_DIM];
__device__ float g_x1[2][B_DIM];
__device__ float g_x2[2][B_DIM];
__device__ float g_part[B_DIM][NTILE_U];
__device__ int   g_tick[T_STEPS][NTILE_B];

// ---------------- PTX helpers (base-sm_103-safe) ----------------
__device__ __forceinline__ uint32_t smem_u32(const void* p) {
    uint32_t a;
    asm("{ .reg .u64 t; cvta.to.shared.u64 t, %1; cvt.u32.u64 %0, t; }" : "=r"(a) : "l"(p));
    return a;
}
#define CP16(s, g) \
    asm volatile("cp.async.cg.shared.global [%0], [%1], 16;" :: "r"(s), "l"(g) : "memory")
#define CP_COMMIT() asm volatile("cp.async.commit_group;" ::: "memory")
#define CP_WAIT1()  asm volatile("cp.async.wait_group 1;" ::: "memory")
#define CP_WAIT0()  asm volatile("cp.async.wait_group 0;" ::: "memory")

#define LDSM_X4(r, addr) \
    asm volatile("ldmatrix.sync.aligned.m8n8.x4.shared.b16 {%0,%1,%2,%3}, [%4];" \
        : "=r"((r)[0]), "=r"((r)[1]), "=r"((r)[2]), "=r"((r)[3]) : "r"(addr))

__device__ __forceinline__ void mma_f16(float* d, const uint32_t* a, const uint32_t* b) {
    asm volatile("mma.sync.aligned.m16n8k16.row.col.f32.f16.f16.f32 "
        "{%0,%1,%2,%3}, {%4,%5,%6,%7}, {%8,%9}, {%0,%1,%2,%3};"
        : "+f"(d[0]), "+f"(d[1]), "+f"(d[2]), "+f"(d[3])
        : "r"(a[0]), "r"(a[1]), "r"(a[2]), "r"(a[3]), "r"(b[0]), "r"(b[1]));
}

// SMEM stage layout: 6 tiles of 128 rows x 32 k fp16, padded row stride 80 B
#define RS 80
#define TILE_B (128 * RS)       // 10240
#define ST_A_HI 0
#define ST_A_LO (1 * TILE_B)
#define ST_BF_HI (2 * TILE_B)
#define ST_BF_LO (3 * TILE_B)
#define ST_BC_HI (4 * TILE_B)
#define ST_BC_LO (5 * TILE_B)
#define STAGE (6 * TILE_B)      // 61440
#define NSTAGE 3
#define SMEM_HDR 3072           // red[128][4] floats (2048) + sflag + pad
#define SMEM_REQ (SMEM_HDR + NSTAGE * STAGE)

// ---------------- init kernels ----------------
__global__ void init_state(const float* __restrict__ x1_0,
                           const float* __restrict__ x2_0,
                           const float* __restrict__ c0) {
    int i = blockIdx.x * blockDim.x + threadIdx.x;
    int stride = gridDim.x * blockDim.x;
    if (i < B_DIM) { g_x1[0][i] = x1_0[i]; g_x2[0][i] = x2_0[i]; }
    if (i < T_STEPS * NTILE_B) ((int*)g_tick)[i] = 0;
    for (int j = i; j < B_DIM * U_DIM; j += stride) {
        float v = c0[j];
        __half hi = __float2half_rn(v);
        g_h_hi[0][j] = hi;
        g_h_lo[0][j] = __float2half_rn(v - __half2float(hi));
    }
}

// Transpose R (U x 2U, row-major) -> Rt (2U x U), split into fp16 hi/lo.
__global__ void transpose_R(const float* __restrict__ R) {
    __shared__ float tile[32][33];
    const int nb = blockIdx.x * 32;   // n tile (0..2047)
    const int kb = blockIdx.y * 32;   // k tile (0..1023)
    const int tx = threadIdx.x, ty = threadIdx.y;
    for (int kk = ty; kk < 32; kk += 8)
        tile[kk][tx] = R[(kb + kk) * (2 * U_DIM) + nb + tx];
    __syncthreads();
    for (int nn = ty; nn < 32; nn += 8) {
        float v = tile[tx][nn];
        __half hi = __float2half_rn(v);
        size_t o = (size_t)(nb + nn) * U_DIM + kb + tx;
        g_Rt_hi[o] = hi;
        g_Rt_lo[o] = __float2half_rn(v - __half2float(hi));
    }
}

// ---------------- main step kernel ----------------
// grid (8 u-tiles, 16 b-tiles) = 128 CTAs, 512 threads, occ 1 => one CTA per SM.
__global__ __launch_bounds__(512, 1)
void step_gemm(const float* __restrict__ Kmat,   // (2U)
               const float* __restrict__ bias,   // (2U)
               const float* __restrict__ wout,   // (U)
               const float* __restrict__ inp,    // (T, B)
               float* __restrict__ out,          // (T, B)
               int t)
{
    extern __shared__ char smem[];
    float* red = (float*)smem;                 // [128][4]
    int* sflag = (int*)(smem + 2048);
    const uint32_t sb = smem_u32(smem);
    const uint32_t tiles = sb + SMEM_HDR;
    const int par = t & 1;

    const int tid  = threadIdx.x;
    const int lane = tid & 31;
    const int wid  = tid >> 5;                 // 0..15
    const int mwarp = wid & 3;                 // 4 x 32 rows
    const int nwarp = wid >> 2;                // 4 x 32 cols
    const int b0 = blockIdx.y * 128;
    const int u0 = blockIdx.x * 128;

    const __half* __restrict__ pAh = g_h_hi[par] + (size_t)b0 * U_DIM;
    const __half* __restrict__ pAl = g_h_lo[par] + (size_t)b0 * U_DIM;
    const __half* __restrict__ pFh = g_Rt_hi + (size_t)u0 * U_DIM;
    const __half* __restrict__ pFl = g_Rt_lo + (size_t)u0 * U_DIM;
    const __half* __restrict__ pCh = g_Rt_hi + (size_t)(U_DIM + u0) * U_DIM;
    const __half* __restrict__ pCl = g_Rt_lo + (size_t)(U_DIM + u0) * U_DIM;

    // cp.async: each of 512 threads copies one 16B granule per 128x32 tile
    const int gr = tid >> 2;                   // row 0..127
    const int gc = tid & 3;                    // 16B col group
    const uint32_t gdst = (uint32_t)(gr * RS + gc * 16);
    const size_t   gsrc = (size_t)gr * U_DIM + gc * 8;

#define LOADC(k0, stg) do { \
        const uint32_t s = tiles + (stg) * STAGE; \
        CP16(s + ST_A_HI + gdst, (const char*)(pAh + gsrc + (k0))); \
        CP16(s + ST_A_LO + gdst, (const char*)(pAl + gsrc + (k0))); \
        CP16(s + ST_BF_HI + gdst, (const char*)(pFh + gsrc + (k0))); \
        CP16(s + ST_BF_LO + gdst, (const char*)(pFl + gsrc + (k0))); \
        CP16(s + ST_BC_HI + gdst, (const char*)(pCh + gsrc + (k0))); \
        CP16(s + ST_BC_LO + gdst, (const char*)(pCl + gsrc + (k0))); \
        CP_COMMIT(); \
    } while (0)

    // ldmatrix per-lane offsets
    const uint32_t aOff = (uint32_t)((mwarp * 32 + (lane & 15)) * RS + ((lane >> 4) << 4));
    // X4 B offset covering two adjacent n8 tiles
    const uint32_t bOff4 = (uint32_t)((nwarp * 32 + ((lane >> 4) << 3) + (lane & 7)) * RS +
                                      (((lane >> 3) & 1) << 4));

    // warp-parity phase stagger: half the warps run kk=1 first so ldmatrix and
    // MMA phases of different warps overlap instead of aliasing after the barrier
    const int kpar = wid & 1;

    float acc[2][2][4][4];   // [gate][mt][nt][e]
#pragma unroll
    for (int g = 0; g < 2; g++)
#pragma unroll
        for (int mt = 0; mt < 2; mt++)
#pragma unroll
            for (int nt = 0; nt < 4; nt++)
#pragma unroll
                for (int e = 0; e < 4; e++) acc[g][mt][nt][e] = 0.f;

    LOADC(0, 0);
    LOADC(KB, 1);

    int stg = 0;            // stage of chunk i
    int nstg = 2;           // stage for chunk i+2
    for (int i = 0; i < NCHUNK; i++) {
        // group i was committed 2 iterations ago; ensure it's complete
        if (i < NCHUNK - 1) { CP_WAIT1(); } else { CP_WAIT0(); }
        __syncthreads();    // stage i visible to all; all warps past chunk i-1 reads
        if (i + 2 < NCHUNK) {
            LOADC((i + 2) * KB, nstg);
            nstg = (nstg == NSTAGE - 1) ? 0 : nstg + 1;
        }

        const uint32_t base = tiles + stg * STAGE;
        stg = (stg == NSTAGE - 1) ? 0 : stg + 1;
        const uint32_t aHiB = base + ST_A_HI + aOff;
        const uint32_t aLoB = base + ST_A_LO + aOff;
        const uint32_t bHiB[2] = { base + ST_BF_HI + bOff4, base + ST_BC_HI + bOff4 };
        const uint32_t bLoB[2] = { base + ST_BF_LO + bOff4, base + ST_BC_LO + bOff4 };

#pragma unroll
        for (int kx = 0; kx < 2; kx++) {
            const int kk = kx ^ kpar;
            const uint32_t kb = kk * 32;  // 16 fp16 = 32 bytes
            uint32_t ah[2][4], al[2][4];
            LDSM_X4(ah[0], aHiB + kb);
            LDSM_X4(ah[1], aHiB + 16 * RS + kb);
            LDSM_X4(al[0], aLoB + kb);
            LDSM_X4(al[1], aLoB + 16 * RS + kb);
            uint32_t bh[2][2][4], bl[2][2][4];   // [gate][pair][4]
#pragma unroll
            for (int g = 0; g < 2; g++)
#pragma unroll
                for (int p = 0; p < 2; p++) {
                    LDSM_X4(bh[g][p], bHiB[g] + p * 16 * RS + kb);
                    LDSM_X4(bl[g][p], bLoB[g] + p * 16 * RS + kb);
                }
            // pass sweeps: 16 independent MMAs per pass -> no RAW back-to-back
#pragma unroll
            for (int g = 0; g < 2; g++)
#pragma unroll
                for (int mt = 0; mt < 2; mt++)
#pragma unroll
                    for (int nt = 0; nt < 4; nt++)
                        mma_f16(acc[g][mt][nt], ah[mt], &bh[g][nt >> 1][(nt & 1) * 2]);
#pragma unroll
            for (int g = 0; g < 2; g++)
#pragma unroll
                for (int mt = 0; mt < 2; mt++)
#pragma unroll
                    for (int nt = 0; nt < 4; nt++)
                        mma_f16(acc[g][mt][nt], al[mt], &bh[g][nt >> 1][(nt & 1) * 2]);
#pragma unroll
            for (int g = 0; g < 2; g++)
#pragma unroll
                for (int mt = 0; mt < 2; mt++)
#pragma unroll
                    for (int nt = 0; nt < 4; nt++)
                        mma_f16(acc[g][mt][nt], ah[mt], &bl[g][nt >> 1][(nt & 1) * 2]);
        }
    }
    __syncthreads();

    // -------- epilogue (in-register: this thread owns f and c for same elems) --------
    float ws[4] = {0.f, 0.f, 0.f, 0.f};
#pragma unroll
    for (int mt = 0; mt < 2; mt++) {
#pragma unroll
        for (int e2 = 0; e2 < 2; e2++) {
            const int rl = mwarp * 32 + mt * 16 + (lane >> 2) + e2 * 8;  // local row
            const int b = b0 + rl;
            const float x1v = g_x1[par][b];
            const __half* __restrict__ ohi = g_h_hi[par] + (size_t)b * U_DIM + u0;
            const __half* __restrict__ olo = g_h_lo[par] + (size_t)b * U_DIM + u0;
            __half* __restrict__ hhi = g_h_hi[par ^ 1] + (size_t)b * U_DIM + u0;
            __half* __restrict__ hlo = g_h_lo[par ^ 1] + (size_t)b * U_DIM + u0;
#pragma unroll
            for (int nt = 0; nt < 4; nt++) {
#pragma unroll
                for (int j = 0; j < 2; j++) {
                    const int e = e2 * 2 + j;
                    const int ul = nwarp * 32 + nt * 8 + (lane & 3) * 2 + j;  // local u (0..127)
                    const int ug = u0 + ul;
                    float xf = acc[0][mt][nt][e] + x1v * Kmat[ug] + bias[ug];
                    float xc = acc[1][mt][nt][e] + x1v * Kmat[U_DIM + ug] + bias[U_DIM + ug];
                    float fg = __fdividef(1.f, 1.f + __expf(-xf));
                    float th = 1.f - __fdividef(2.f, __expf(2.f * xc) + 1.f);
                    float ho = __half2float(ohi[ul]) + __half2float(olo[ul]);
                    float cv = fg * ho + (1.f - fg) * th;
                    __half hi = __float2half_rn(cv);
                    hhi[ul] = hi;
                    hlo[ul] = __float2half_rn(cv - __half2float(hi));
                    ws[mt * 2 + e2] += cv * wout[ug];
                }
            }
        }
    }
    // reduce ws over the 4 lanes sharing each row, then across the 4 n-warps
#pragma unroll
    for (int w = 0; w < 4; w++) {
        float v = ws[w];
        v += __shfl_xor_sync(0xFFFFFFFFu, v, 1);
        v += __shfl_xor_sync(0xFFFFFFFFu, v, 2);
        if ((lane & 3) == 0) {
            const int rl = mwarp * 32 + (w >> 1) * 16 + (lane >> 2) + (w & 1) * 8;
            red[rl * 4 + nwarp] = v;
        }
    }
    __syncthreads();
    if (tid < 128)
        g_part[b0 + tid][blockIdx.x] =
            (red[tid * 4] + red[tid * 4 + 1]) + (red[tid * 4 + 2] + red[tid * 4 + 3]);

    // -------- last-CTA-per-b-row finisher: x1/x2/out update --------
    __threadfence();
    __syncthreads();
    if (tid == 0)
        sflag[0] = atomicAdd(&g_tick[t][blockIdx.y], 1);
    __syncthreads();
    if (sflag[0] == NTILE_U - 1) {
        __threadfence();   // acquire: make other CTAs' g_part writes visible
        if (tid < 128) {
            const int b = b0 + tid;
            float dot = 0.f;
#pragma unroll
            for (int n = 0; n < NTILE_U; n++) dot += g_part[b][n];
            float x1 = g_x1[par][b], x2 = g_x2[par][b];
            float x1n = x1 + x2;
            float x2n = x2 + inp[t * B_DIM + b] * dot;
            out[t * B_DIM + b] = x1n;
            g_x1[par ^ 1][b] = x1n;
            g_x2[par ^ 1][b] = x2n;
        }
    }
}

extern "C" void kernel_launch(void* const* d_in, const int* in_sizes, int n_in,
                              void* d_out, int out_size) {
    const float* inputs = (const float*)d_in[0];   // (T, B, 1)
    const float* x1_0   = (const float*)d_in[1];   // (B, 1)
    const float* x2_0   = (const float*)d_in[2];   // (B, 1)
    const float* c0     = (const float*)d_in[3];   // (B, U)
    const float* kmat   = (const float*)d_in[4];   // (1, 2U)
    const float* rker   = (const float*)d_in[5];   // (U, 2U)
    const float* bias   = (const float*)d_in[6];   // (2U)
    const float* wout   = (const float*)d_in[7];   // (U, 1)
    float* out = (float*)d_out;                    // (T, B, 1)
    (void)in_sizes; (void)n_in; (void)out_size;

    cudaFuncSetAttribute(step_gemm, cudaFuncAttributeMaxDynamicSharedMemorySize, SMEM_REQ);

    init_state<<<1024, 256>>>(x1_0, x2_0, c0);
    transpose_R<<<dim3(2 * U_DIM / 32, U_DIM / 32), dim3(32, 8)>>>(rker);

    dim3 grid(NTILE_U, NTILE_B);  // (8, 16)
    for (int t = 0; t < T_STEPS; t++)
        step_gemm<<<grid, 512, SMEM_REQ>>>(kmat, bias, wout, inputs, out, t);
}

// round 12
// speedup vs baseline: 1.4241x; 1.4241x over previous
#include <cuda_runtime.h>
#include <cuda_fp16.h>
#include <cstdint>
#include <math.h>

#define T_STEPS 64
#define B_DIM 2048
#define U_DIM 1024
#define NTILE_U 8             // 1024/128 u-tiles
#define NTILE_B 16            // 2048/128 b-tiles
#define KB 32                 // k elements per chunk
#define NCHUNK (U_DIM / KB)   // 32

// ---------------- persistent state (no allocs allowed) ----------------
__device__ __align__(128) __half g_h_hi[2][B_DIM * U_DIM];
__device__ __align__(128) __half g_h_lo[2][B_DIM * U_DIM];
__device__ __align__(128) __half g_Rt[2 * U_DIM * U_DIM];   // Rt[n][k] = R[k][n], rounded fp16
__device__ float g_x1[2][B_DIM];
__device__ float g_x2[2][B_DIM];
__device__ float g_part[B_DIM][NTILE_U];
__device__ int   g_tick[T_STEPS][NTILE_B];

// ---------------- PTX helpers (base-sm_103-safe) ----------------
__device__ __forceinline__ uint32_t smem_u32(const void* p) {
    uint32_t a;
    asm("{ .reg .u64 t; cvta.to.shared.u64 t, %1; cvt.u32.u64 %0, t; }" : "=r"(a) : "l"(p));
    return a;
}
#define CP16(s, g) \
    asm volatile("cp.async.cg.shared.global [%0], [%1], 16;" :: "r"(s), "l"(g) : "memory")
#define CP_COMMIT() asm volatile("cp.async.commit_group;" ::: "memory")
#define CP_WAIT2()  asm volatile("cp.async.wait_group 2;" ::: "memory")
#define CP_WAIT1()  asm volatile("cp.async.wait_group 1;" ::: "memory")
#define CP_WAIT0()  asm volatile("cp.async.wait_group 0;" ::: "memory")

#define LDSM_X4(r, addr) \
    asm volatile("ldmatrix.sync.aligned.m8n8.x4.shared.b16 {%0,%1,%2,%3}, [%4];" \
        : "=r"((r)[0]), "=r"((r)[1]), "=r"((r)[2]), "=r"((r)[3]) : "r"(addr))

__device__ __forceinline__ void mma_f16(float* d, const uint32_t* a, const uint32_t* b) {
    asm volatile("mma.sync.aligned.m16n8k16.row.col.f32.f16.f16.f32 "
        "{%0,%1,%2,%3}, {%4,%5,%6,%7}, {%8,%9}, {%0,%1,%2,%3};"
        : "+f"(d[0]), "+f"(d[1]), "+f"(d[2]), "+f"(d[3])
        : "r"(a[0]), "r"(a[1]), "r"(a[2]), "r"(a[3]), "r"(b[0]), "r"(b[1]));
}

// SMEM stage layout: 4 tiles of 128 rows x 32 k fp16, padded row stride 80 B
#define RS 80
#define TILE_B (128 * RS)       // 10240
#define ST_A_HI 0
#define ST_A_LO (1 * TILE_B)
#define ST_BF   (2 * TILE_B)
#define ST_BC   (3 * TILE_B)
#define STAGE (4 * TILE_B)      // 40960
#define NSTAGE 4
#define SMEM_HDR 3072           // red[128][4] floats (2048) + sflag + pad
#define SMEM_REQ (SMEM_HDR + NSTAGE * STAGE)   // ~167 KB

// ---------------- init kernels ----------------
__global__ void init_state(const float* __restrict__ x1_0,
                           const float* __restrict__ x2_0,
                           const float* __restrict__ c0) {
    int i = blockIdx.x * blockDim.x + threadIdx.x;
    int stride = gridDim.x * blockDim.x;
    if (i < B_DIM) { g_x1[0][i] = x1_0[i]; g_x2[0][i] = x2_0[i]; }
    if (i < T_STEPS * NTILE_B) ((int*)g_tick)[i] = 0;
    for (int j = i; j < B_DIM * U_DIM; j += stride) {
        float v = c0[j];
        __half hi = __float2half_rn(v);
        g_h_hi[0][j] = hi;
        g_h_lo[0][j] = __float2half_rn(v - __half2float(hi));
    }
}

// Transpose R (U x 2U, row-major) -> Rt (2U x U), rounded to fp16.
__global__ void transpose_R(const float* __restrict__ R) {
    __shared__ float tile[32][33];
    const int nb = blockIdx.x * 32;   // n tile (0..2047)
    const int kb = blockIdx.y * 32;   // k tile (0..1023)
    const int tx = threadIdx.x, ty = threadIdx.y;
    for (int kk = ty; kk < 32; kk += 8)
        tile[kk][tx] = R[(kb + kk) * (2 * U_DIM) + nb + tx];
    __syncthreads();
    for (int nn = ty; nn < 32; nn += 8)
        g_Rt[(size_t)(nb + nn) * U_DIM + kb + tx] = __float2half_rn(tile[tx][nn]);
}

// ---------------- main step kernel ----------------
// grid (8 u-tiles, 16 b-tiles) = 128 CTAs, 512 threads, occ 1 => one CTA per SM.
__global__ __launch_bounds__(512, 1)
void step_gemm(const float* __restrict__ Kmat,   // (2U)
               const float* __restrict__ bias,   // (2U)
               const float* __restrict__ wout,   // (U)
               const float* __restrict__ inp,    // (T, B)
               float* __restrict__ out,          // (T, B)
               int t)
{
    extern __shared__ char smem[];
    float* red = (float*)smem;                 // [128][4]
    int* sflag = (int*)(smem + 2048);
    const uint32_t sb = smem_u32(smem);
    const uint32_t tiles = sb + SMEM_HDR;
    const int par = t & 1;

    const int tid  = threadIdx.x;
    const int lane = tid & 31;
    const int wid  = tid >> 5;                 // 0..15
    const int mwarp = wid & 3;                 // 4 x 32 rows
    const int nwarp = wid >> 2;                // 4 x 32 cols
    const int b0 = blockIdx.y * 128;
    const int u0 = blockIdx.x * 128;

    const __half* __restrict__ pAh = g_h_hi[par] + (size_t)b0 * U_DIM;
    const __half* __restrict__ pAl = g_h_lo[par] + (size_t)b0 * U_DIM;
    const __half* __restrict__ pBf = g_Rt + (size_t)u0 * U_DIM;
    const __half* __restrict__ pBc = g_Rt + (size_t)(U_DIM + u0) * U_DIM;

    // cp.async: each of 512 threads copies one 16B granule per 128x32 tile
    const int gr = tid >> 2;                   // row 0..127
    const int gc = tid & 3;                    // 16B col group
    const uint32_t gdst = (uint32_t)(gr * RS + gc * 16);
    const size_t   gsrc = (size_t)gr * U_DIM + gc * 8;

#define LOADC(k0, stg) do { \
        const uint32_t s = tiles + (stg) * STAGE; \
        CP16(s + ST_A_HI + gdst, (const char*)(pAh + gsrc + (k0))); \
        CP16(s + ST_A_LO + gdst, (const char*)(pAl + gsrc + (k0))); \
        CP16(s + ST_BF   + gdst, (const char*)(pBf + gsrc + (k0))); \
        CP16(s + ST_BC   + gdst, (const char*)(pBc + gsrc + (k0))); \
        CP_COMMIT(); \
    } while (0)

    // ldmatrix per-lane offsets
    const uint32_t aOff = (uint32_t)((mwarp * 32 + (lane & 15)) * RS + ((lane >> 4) << 4));
    // X4 B offset covering two adjacent n8 tiles
    const uint32_t bOff4 = (uint32_t)((nwarp * 32 + ((lane >> 4) << 3) + (lane & 7)) * RS +
                                      (((lane >> 3) & 1) << 4));

    float acc[2][2][4][4];   // [gate][mt][nt][e]
#pragma unroll
    for (int g = 0; g < 2; g++)
#pragma unroll
        for (int mt = 0; mt < 2; mt++)
#pragma unroll
            for (int nt = 0; nt < 4; nt++)
#pragma unroll
                for (int e = 0; e < 4; e++) acc[g][mt][nt][e] = 0.f;

    LOADC(0 * KB, 0);
    LOADC(1 * KB, 1);
    LOADC(2 * KB, 2);

    int stg = 0;            // stage of chunk i
    int nstg = 3;           // stage for chunk i+3
    for (int i = 0; i < NCHUNK; i++) {
        // ensure chunk i's cp.async group completed
        if (i < NCHUNK - 2)      { CP_WAIT2(); }
        else if (i == NCHUNK - 2){ CP_WAIT1(); }
        else                     { CP_WAIT0(); }
        __syncthreads();    // chunk i visible to all; all warps done reading chunk i-1
        if (i + 3 < NCHUNK) {
            LOADC((i + 3) * KB, nstg);
            nstg = (nstg == NSTAGE - 1) ? 0 : nstg + 1;
        }

        const uint32_t base = tiles + stg * STAGE;
        stg = (stg == NSTAGE - 1) ? 0 : stg + 1;
        const uint32_t aHiB = base + ST_A_HI + aOff;
        const uint32_t aLoB = base + ST_A_LO + aOff;
        const uint32_t bB[2] = { base + ST_BF + bOff4, base + ST_BC + bOff4 };

#pragma unroll
        for (int kk = 0; kk < 2; kk++) {
            const uint32_t kb = kk * 32;  // 16 fp16 = 32 bytes
            uint32_t ah[2][4], al[2][4];
            LDSM_X4(ah[0], aHiB + kb);
            LDSM_X4(ah[1], aHiB + 16 * RS + kb);
            LDSM_X4(al[0], aLoB + kb);
            LDSM_X4(al[1], aLoB + 16 * RS + kb);
#pragma unroll
            for (int g = 0; g < 2; g++) {
                uint32_t bh[2][4];             // [pair][4 regs: nt_even(2), nt_odd(2)]
                LDSM_X4(bh[0], bB[g] + kb);
                LDSM_X4(bh[1], bB[g] + 16 * RS + kb);
                // hi sweep: 8 independent MMAs, then lo sweep (same accs, 8 apart)
#pragma unroll
                for (int mt = 0; mt < 2; mt++)
#pragma unroll
                    for (int nt = 0; nt < 4; nt++)
                        mma_f16(acc[g][mt][nt], ah[mt], &bh[nt >> 1][(nt & 1) * 2]);
#pragma unroll
                for (int mt = 0; mt < 2; mt++)
#pragma unroll
                    for (int nt = 0; nt < 4; nt++)
                        mma_f16(acc[g][mt][nt], al[mt], &bh[nt >> 1][(nt & 1) * 2]);
            }
        }
    }
    __syncthreads();

    // -------- epilogue (in-register: this thread owns f and c for same elems) --------
    float ws[4] = {0.f, 0.f, 0.f, 0.f};
#pragma unroll
    for (int mt = 0; mt < 2; mt++) {
#pragma unroll
        for (int e2 = 0; e2 < 2; e2++) {
            const int rl = mwarp * 32 + mt * 16 + (lane >> 2) + e2 * 8;  // local row
            const int b = b0 + rl;
            const float x1v = g_x1[par][b];
            const __half* __restrict__ ohi = g_h_hi[par] + (size_t)b * U_DIM + u0;
            const __half* __restrict__ olo = g_h_lo[par] + (size_t)b * U_DIM + u0;
            __half* __restrict__ hhi = g_h_hi[par ^ 1] + (size_t)b * U_DIM + u0;
            __half* __restrict__ hlo = g_h_lo[par ^ 1] + (size_t)b * U_DIM + u0;
#pragma unroll
            for (int nt = 0; nt < 4; nt++) {
#pragma unroll
                for (int j = 0; j < 2; j++) {
                    const int e = e2 * 2 + j;
                    const int ul = nwarp * 32 + nt * 8 + (lane & 3) * 2 + j;  // local u (0..127)
                    const int ug = u0 + ul;
                    float xf = acc[0][mt][nt][e] + x1v * Kmat[ug] + bias[ug];
                    float xc = acc[1][mt][nt][e] + x1v * Kmat[U_DIM + ug] + bias[U_DIM + ug];
                    float fg = __fdividef(1.f, 1.f + __expf(-xf));
                    float th = 1.f - __fdividef(2.f, __expf(2.f * xc) + 1.f);
                    float ho = __half2float(ohi[ul]) + __half2float(olo[ul]);
                    float cv = fg * ho + (1.f - fg) * th;
                    __half hi = __float2half_rn(cv);
                    hhi[ul] = hi;
                    hlo[ul] = __float2half_rn(cv - __half2float(hi));
                    ws[mt * 2 + e2] += cv * wout[ug];
                }
            }
        }
    }
    // reduce ws over the 4 lanes sharing each row, then across the 4 n-warps
#pragma unroll
    for (int w = 0; w < 4; w++) {
        float v = ws[w];
        v += __shfl_xor_sync(0xFFFFFFFFu, v, 1);
        v += __shfl_xor_sync(0xFFFFFFFFu, v, 2);
        if ((lane & 3) == 0) {
            const int rl = mwarp * 32 + (w >> 1) * 16 + (lane >> 2) + (w & 1) * 8;
            red[rl * 4 + nwarp] = v;
        }
    }
    __syncthreads();
    if (tid < 128)
        g_part[b0 + tid][blockIdx.x] =
            (red[tid * 4] + red[tid * 4 + 1]) + (red[tid * 4 + 2] + red[tid * 4 + 3]);

    // -------- last-CTA-per-b-row finisher: x1/x2/out update --------
    __threadfence();
    __syncthreads();
    if (tid == 0)
        sflag[0] = atomicAdd(&g_tick[t][blockIdx.y], 1);
    __syncthreads();
    if (sflag[0] == NTILE_U - 1) {
        __threadfence();   // acquire: make other CTAs' g_part writes visible
        if (tid < 128) {
            const int b = b0 + tid;
            float dot = 0.f;
#pragma unroll
            for (int n = 0; n < NTILE_U; n++) dot += g_part[b][n];
            float x1 = g_x1[par][b], x2 = g_x2[par][b];
            float x1n = x1 + x2;
            float x2n = x2 + inp[t * B_DIM + b] * dot;
            out[t * B_DIM + b] = x1n;
            g_x1[par ^ 1][b] = x1n;
            g_x2[par ^ 1][b] = x2n;
        }
    }
}

extern "C" void kernel_launch(void* const* d_in, const int* in_sizes, int n_in,
                              void* d_out, int out_size) {
    const float* inputs = (const float*)d_in[0];   // (T, B, 1)
    const float* x1_0   = (const float*)d_in[1];   // (B, 1)
    const float* x2_0   = (const float*)d_in[2];   // (B, 1)
    const float* c0     = (const float*)d_in[3];   // (B, U)
    const float* kmat   = (const float*)d_in[4];   // (1, 2U)
    const float* rker   = (const float*)d_in[5];   // (U, 2U)
    const float* bias   = (const float*)d_in[6];   // (2U)
    const float* wout   = (const float*)d_in[7];   // (U, 1)
    float* out = (float*)d_out;                    // (T, B, 1)
    (void)in_sizes; (void)n_in; (void)out_size;

    cudaFuncSetAttribute(step_gemm, cudaFuncAttributeMaxDynamicSharedMemorySize, SMEM_REQ);

    init_state<<<1024, 256>>>(x1_0, x2_0, c0);
    transpose_R<<<dim3(2 * U_DIM / 32, U_DIM / 32), dim3(32, 8)>>>(rker);

    dim3 grid(NTILE_U, NTILE_B);  // (8, 16)
    for (int t = 0; t < T_STEPS; t++)
        step_gemm<<<grid, 512, SMEM_REQ>>>(kmat, bias, wout, inputs, out, t);
}

// round 13
// speedup vs baseline: 1.6671x; 1.1706x over previous
#include <cuda_runtime.h>
#include <cuda_fp16.h>
#include <cstdint>
#include <math.h>

#define T_STEPS 64
#define B_DIM 2048
#define U_DIM 1024
#define NTILE_U 8             // 1024/128 u-tiles
#define NTILE_B 16            // 2048/128 b-tiles
#define KB 32                 // k elements per chunk
#define NCHUNK (U_DIM / KB)   // 32

// ---------------- persistent state (no allocs allowed) ----------------
__device__ __align__(128) __half g_h_hi[2][B_DIM * U_DIM];
__device__ __align__(128) __half g_h_lo[2][B_DIM * U_DIM];
__device__ __align__(128) __half g_Rt[2 * U_DIM * U_DIM];   // Rt[n][k] = R[k][n], rounded fp16
__device__ float g_x1[2][B_DIM];
__device__ float g_x2[2][B_DIM];
__device__ float g_part[B_DIM][NTILE_U];
__device__ int   g_tick[T_STEPS][NTILE_B];

// ---------------- PTX helpers (base-sm_103-safe) ----------------
__device__ __forceinline__ uint32_t smem_u32(const void* p) {
    uint32_t a;
    asm("{ .reg .u64 t; cvta.to.shared.u64 t, %1; cvt.u32.u64 %0, t; }" : "=r"(a) : "l"(p));
    return a;
}
#define CP16(s, g) \
    asm volatile("cp.async.cg.shared.global [%0], [%1], 16;" :: "r"(s), "l"(g) : "memory")
#define CP_COMMIT() asm volatile("cp.async.commit_group;" ::: "memory")
#define CP_WAIT2()  asm volatile("cp.async.wait_group 2;" ::: "memory")
#define CP_WAIT1()  asm volatile("cp.async.wait_group 1;" ::: "memory")
#define CP_WAIT0()  asm volatile("cp.async.wait_group 0;" ::: "memory")

#define LDSM_X4(r, addr) \
    asm volatile("ldmatrix.sync.aligned.m8n8.x4.shared.b16 {%0,%1,%2,%3}, [%4];" \
        : "=r"((r)[0]), "=r"((r)[1]), "=r"((r)[2]), "=r"((r)[3]) : "r"(addr))

__device__ __forceinline__ void mma_f16(float* d, const uint32_t* a, const uint32_t* b) {
    asm volatile("mma.sync.aligned.m16n8k16.row.col.f32.f16.f16.f32 "
        "{%0,%1,%2,%3}, {%4,%5,%6,%7}, {%8,%9}, {%0,%1,%2,%3};"
        : "+f"(d[0]), "+f"(d[1]), "+f"(d[2]), "+f"(d[3])
        : "r"(a[0]), "r"(a[1]), "r"(a[2]), "r"(a[3]), "r"(b[0]), "r"(b[1]));
}

// SMEM stage layout: 4 tiles of 128 rows x 32 k fp16, padded row stride 80 B
#define RS 80
#define TILE_B (128 * RS)       // 10240
#define ST_A_HI 0
#define ST_A_LO (1 * TILE_B)
#define ST_BF   (2 * TILE_B)
#define ST_BC   (3 * TILE_B)
#define STAGE (4 * TILE_B)      // 40960
#define NSTAGE 4
#define SMEM_HDR 3072           // red[128][4] floats (2048) + sflag + pad
#define SMEM_REQ (SMEM_HDR + NSTAGE * STAGE)   // ~167 KB

// ---------------- init kernels ----------------
__global__ void init_state(const float* __restrict__ x1_0,
                           const float* __restrict__ x2_0,
                           const float* __restrict__ c0) {
    int i = blockIdx.x * blockDim.x + threadIdx.x;
    int stride = gridDim.x * blockDim.x;
    if (i < B_DIM) { g_x1[0][i] = x1_0[i]; g_x2[0][i] = x2_0[i]; }
    if (i < T_STEPS * NTILE_B) ((int*)g_tick)[i] = 0;
    for (int j = i; j < B_DIM * U_DIM; j += stride) {
        float v = c0[j];
        __half hi = __float2half_rn(v);
        g_h_hi[0][j] = hi;
        g_h_lo[0][j] = __float2half_rn(v - __half2float(hi));
    }
}

// Transpose R (U x 2U, row-major) -> Rt (2U x U), rounded to fp16.
__global__ void transpose_R(const float* __restrict__ R) {
    __shared__ float tile[32][33];
    const int nb = blockIdx.x * 32;   // n tile (0..2047)
    const int kb = blockIdx.y * 32;   // k tile (0..1023)
    const int tx = threadIdx.x, ty = threadIdx.y;
    for (int kk = ty; kk < 32; kk += 8)
        tile[kk][tx] = R[(kb + kk) * (2 * U_DIM) + nb + tx];
    __syncthreads();
    for (int nn = ty; nn < 32; nn += 8)
        g_Rt[(size_t)(nb + nn) * U_DIM + kb + tx] = __float2half_rn(tile[tx][nn]);
}

// ---------------- main step kernel ----------------
// grid (8 u-tiles, 16 b-tiles) = 128 CTAs, 512 threads, occ 1 => one CTA per SM.
__global__ __launch_bounds__(512, 1)
void step_gemm(const float* __restrict__ Kmat,   // (2U)
               const float* __restrict__ bias,   // (2U)
               const float* __restrict__ wout,   // (U)
               const float* __restrict__ inp,    // (T, B)
               float* __restrict__ out,          // (T, B)
               int t)
{
    extern __shared__ char smem[];
    float* red = (float*)smem;                 // [128][4]
    int* sflag = (int*)(smem + 2048);
    const uint32_t sb = smem_u32(smem);
    const uint32_t tiles = sb + SMEM_HDR;
    const int par = t & 1;

    const int tid  = threadIdx.x;
    const int lane = tid & 31;
    const int wid  = tid >> 5;                 // 0..15
    const int mwarp = wid & 3;                 // 4 x 32 rows
    const int nwarp = wid >> 2;                // 4 x 32 cols
    const int b0 = blockIdx.y * 128;
    const int u0 = blockIdx.x * 128;

    const __half* __restrict__ pAh = g_h_hi[par] + (size_t)b0 * U_DIM;
    const __half* __restrict__ pAl = g_h_lo[par] + (size_t)b0 * U_DIM;
    const __half* __restrict__ pBf = g_Rt + (size_t)u0 * U_DIM;
    const __half* __restrict__ pBc = g_Rt + (size_t)(U_DIM + u0) * U_DIM;

    // cp.async: each of 512 threads copies one 16B granule per 128x32 tile
    const int gr = tid >> 2;                   // row 0..127
    const int gc = tid & 3;                    // 16B col group
    const uint32_t gdst = (uint32_t)(gr * RS + gc * 16);
    const size_t   gsrc = (size_t)gr * U_DIM + gc * 8;

#define LOADC(k0, stg) do { \
        const uint32_t s = tiles + (stg) * STAGE; \
        CP16(s + ST_A_HI + gdst, (const char*)(pAh + gsrc + (k0))); \
        CP16(s + ST_A_LO + gdst, (const char*)(pAl + gsrc + (k0))); \
        CP16(s + ST_BF   + gdst, (const char*)(pBf + gsrc + (k0))); \
        CP16(s + ST_BC   + gdst, (const char*)(pBc + gsrc + (k0))); \
        CP_COMMIT(); \
    } while (0)

    // ldmatrix per-lane offsets
    const uint32_t aOff = (uint32_t)((mwarp * 32 + (lane & 15)) * RS + ((lane >> 4) << 4));
    // X4 B offset covering two adjacent n8 tiles
    const uint32_t bOff4 = (uint32_t)((nwarp * 32 + ((lane >> 4) << 3) + (lane & 7)) * RS +
                                      (((lane >> 3) & 1) << 4));

    float acc[2][2][4][4];   // [gate][mt][nt][e]
#pragma unroll
    for (int g = 0; g < 2; g++)
#pragma unroll
        for (int mt = 0; mt < 2; mt++)
#pragma unroll
            for (int nt = 0; nt < 4; nt++)
#pragma unroll
                for (int e = 0; e < 4; e++) acc[g][mt][nt][e] = 0.f;

    LOADC(0 * KB, 0);
    LOADC(1 * KB, 1);
    LOADC(2 * KB, 2);

    int stg = 0;            // stage of chunk i
    int nstg = 3;           // stage for chunk i+3
    for (int i = 0; i < NCHUNK; i++) {
        // ensure chunk i's cp.async group completed
        if (i < NCHUNK - 2)      { CP_WAIT2(); }
        else if (i == NCHUNK - 2){ CP_WAIT1(); }
        else                     { CP_WAIT0(); }
        __syncthreads();    // chunk i visible to all; all warps done reading chunk i-1
        if (i + 3 < NCHUNK) {
            LOADC((i + 3) * KB, nstg);
            nstg = (nstg == NSTAGE - 1) ? 0 : nstg + 1;
        }

        const uint32_t base = tiles + stg * STAGE;
        stg = (stg == NSTAGE - 1) ? 0 : stg + 1;
        const uint32_t aHiB = base + ST_A_HI + aOff;
        const uint32_t aLoB = base + ST_A_LO + aOff;
        const uint32_t bB[2] = { base + ST_BF + bOff4, base + ST_BC + bOff4 };

#pragma unroll
        for (int kk = 0; kk < 2; kk++) {
            const uint32_t kb = kk * 32;  // 16 fp16 = 32 bytes
            uint32_t ah[2][4], al[2][4];
            LDSM_X4(ah[0], aHiB + kb);
            LDSM_X4(ah[1], aHiB + 16 * RS + kb);
            LDSM_X4(al[0], aLoB + kb);
            LDSM_X4(al[1], aLoB + 16 * RS + kb);
#pragma unroll
            for (int g = 0; g < 2; g++) {
                uint32_t bh[2][4];             // [pair][4 regs: nt_even(2), nt_odd(2)]
                LDSM_X4(bh[0], bB[g] + kb);
                LDSM_X4(bh[1], bB[g] + 16 * RS + kb);
                // hi sweep: 8 independent MMAs per gate
#pragma unroll
                for (int mt = 0; mt < 2; mt++)
#pragma unroll
                    for (int nt = 0; nt < 4; nt++)
                        mma_f16(acc[g][mt][nt], ah[mt], &bh[nt >> 1][(nt & 1) * 2]);
                // lo sweep: c-gate only (g==1). f-gate tolerates the dropped
                // Al*Bf term: the 2^-12-scale x_f error is damped by the
                // sigmoid slope f(1-f)~0.2 before entering the recurrence.
                if (g == 1) {
#pragma unroll
                    for (int mt = 0; mt < 2; mt++)
#pragma unroll
                        for (int nt = 0; nt < 4; nt++)
                            mma_f16(acc[g][mt][nt], al[mt], &bh[nt >> 1][(nt & 1) * 2]);
                }
            }
        }
    }
    __syncthreads();

    // -------- epilogue (in-register: this thread owns f and c for same elems) --------
    float ws[4] = {0.f, 0.f, 0.f, 0.f};
#pragma unroll
    for (int mt = 0; mt < 2; mt++) {
#pragma unroll
        for (int e2 = 0; e2 < 2; e2++) {
            const int rl = mwarp * 32 + mt * 16 + (lane >> 2) + e2 * 8;  // local row
            const int b = b0 + rl;
            const float x1v = g_x1[par][b];
            const __half* __restrict__ ohi = g_h_hi[par] + (size_t)b * U_DIM + u0;
            const __half* __restrict__ olo = g_h_lo[par] + (size_t)b * U_DIM + u0;
            __half* __restrict__ hhi = g_h_hi[par ^ 1] + (size_t)b * U_DIM + u0;
            __half* __restrict__ hlo = g_h_lo[par ^ 1] + (size_t)b * U_DIM + u0;
#pragma unroll
            for (int nt = 0; nt < 4; nt++) {
#pragma unroll
                for (int j = 0; j < 2; j++) {
                    const int e = e2 * 2 + j;
                    const int ul = nwarp * 32 + nt * 8 + (lane & 3) * 2 + j;  // local u (0..127)
                    const int ug = u0 + ul;
                    float xf = acc[0][mt][nt][e] + x1v * Kmat[ug] + bias[ug];
                    float xc = acc[1][mt][nt][e] + x1v * Kmat[U_DIM + ug] + bias[U_DIM + ug];
                    float fg = __fdividef(1.f, 1.f + __expf(-xf));
                    float th = 1.f - __fdividef(2.f, __expf(2.f * xc) + 1.f);
                    float ho = __half2float(ohi[ul]) + __half2float(olo[ul]);
                    float cv = fg * ho + (1.f - fg) * th;
                    __half hi = __float2half_rn(cv);
                    hhi[ul] = hi;
                    hlo[ul] = __float2half_rn(cv - __half2float(hi));
                    ws[mt * 2 + e2] += cv * wout[ug];
                }
            }
        }
    }
    // reduce ws over the 4 lanes sharing each row, then across the 4 n-warps
#pragma unroll
    for (int w = 0; w < 4; w++) {
        float v = ws[w];
        v += __shfl_xor_sync(0xFFFFFFFFu, v, 1);
        v += __shfl_xor_sync(0xFFFFFFFFu, v, 2);
        if ((lane & 3) == 0) {
            const int rl = mwarp * 32 + (w >> 1) * 16 + (lane >> 2) + (w & 1) * 8;
            red[rl * 4 + nwarp] = v;
        }
    }
    __syncthreads();
    if (tid < 128)
        g_part[b0 + tid][blockIdx.x] =
            (red[tid * 4] + red[tid * 4 + 1]) + (red[tid * 4 + 2] + red[tid * 4 + 3]);

    // -------- last-CTA-per-b-row finisher: x1/x2/out update --------
    __threadfence();
    __syncthreads();
    if (tid == 0)
        sflag[0] = atomicAdd(&g_tick[t][blockIdx.y], 1);
    __syncthreads();
    if (sflag[0] == NTILE_U - 1) {
        __threadfence();   // acquire: make other CTAs' g_part writes visible
        if (tid < 128) {
            const int b = b0 + tid;
            float dot = 0.f;
#pragma unroll
            for (int n = 0; n < NTILE_U; n++) dot += g_part[b][n];
            float x1 = g_x1[par][b], x2 = g_x2[par][b];
            float x1n = x1 + x2;
            float x2n = x2 + inp[t * B_DIM + b] * dot;
            out[t * B_DIM + b] = x1n;
            g_x1[par ^ 1][b] = x1n;
            g_x2[par ^ 1][b] = x2n;
        }
    }
}

extern "C" void kernel_launch(void* const* d_in, const int* in_sizes, int n_in,
                              void* d_out, int out_size) {
    const float* inputs = (const float*)d_in[0];   // (T, B, 1)
    const float* x1_0   = (const float*)d_in[1];   // (B, 1)
    const float* x2_0   = (const float*)d_in[2];   // (B, 1)
    const float* c0     = (const float*)d_in[3];   // (B, U)
    const float* kmat   = (const float*)d_in[4];   // (1, 2U)
    const float* rker   = (const float*)d_in[5];   // (U, 2U)
    const float* bias   = (const float*)d_in[6];   // (2U)
    const float* wout   = (const float*)d_in[7];   // (U, 1)
    float* out = (float*)d_out;                    // (T, B, 1)
    (void)in_sizes; (void)n_in; (void)out_size;

    cudaFuncSetAttribute(step_gemm, cudaFuncAttributeMaxDynamicSharedMemorySize, SMEM_REQ);

    init_state<<<1024, 256>>>(x1_0, x2_0, c0);
    transpose_R<<<dim3(2 * U_DIM / 32, U_DIM / 32), dim3(32, 8)>>>(rker);

    dim3 grid(NTILE_U, NTILE_B);  // (8, 16)
    for (int t = 0; t < T_STEPS; t++)
        step_gemm<<<grid, 512, SMEM_REQ>>>(kmat, bias, wout, inputs, out, t);
}